// round 16
// baseline (speedup 1.0000x reference)
#include <cuda_runtime.h>
#include <cuda_bf16.h>
#include <stdint.h>

// ---- problem dims ----
#define TDIM 100
#define MPAD 128
#define KDIM 16384
#define DDIM 8192
#define GCAP 4352
#define NCOLS (2*GCAP)            // 8704

// ---- GEMM tiling: NTILE=128 (R15 proven), chunked K ----
#define NTILE 128
#define KTILE 64
#define KSPLIT 2
#define NCHUNK 4
#define KCHUNK (KDIM/NCHUNK)      // 4096
#define KPER  (KCHUNK/KSPLIT)     // 2048
#define NIT   (KPER/KTILE)        // 32
#define STAGE_BYTES 49152         // A: 2 limbs * 16KB + B: 16KB
#define SMEM_MAIN (3*STAGE_BYTES) // 147456

// ---- scratch ----
__device__ __nv_bfloat16 g_A[2][2][MPAD][KDIM];          // [grp][limb] 16MB
__device__ __nv_bfloat16 g_B[(size_t)KDIM * NCOLS];      // 272MB, [k][col]
__device__ float         g_Wt[(size_t)NCOLS * MPAD];     // [col][m]
__device__ int           g_dcol[DDIM];
__device__ int           g_colmap[NCOLS];
__device__ int           g_cnt[2];
__device__ float         g_partial[NCOLS];

// ---- PTX helpers ----
__device__ __forceinline__ uint32_t smem_u32(const void* p) {
    uint32_t a;
    asm("{ .reg .u64 t; cvta.to.shared.u64 t, %1; cvt.u32.u64 %0, t; }" : "=r"(a) : "l"(p));
    return a;
}
#define CP_ASYNC(dst, src) asm volatile("cp.async.cg.shared.global [%0], [%1], 16;" :: "r"(dst), "l"(src))
#define CP_COMMIT()        asm volatile("cp.async.commit_group;")
#define CP_WAIT1()         asm volatile("cp.async.wait_group 1;")
#define CP_WAIT0()         asm volatile("cp.async.wait_group 0;")

__device__ __forceinline__ void ldsm_x4(uint32_t& r0, uint32_t& r1, uint32_t& r2, uint32_t& r3, uint32_t a) {
    asm volatile("ldmatrix.sync.aligned.m8n8.x4.shared.b16 {%0,%1,%2,%3}, [%4];"
                 : "=r"(r0), "=r"(r1), "=r"(r2), "=r"(r3) : "r"(a));
}
__device__ __forceinline__ void ldsm_x4_t(uint32_t& r0, uint32_t& r1, uint32_t& r2, uint32_t& r3, uint32_t a) {
    asm volatile("ldmatrix.sync.aligned.m8n8.x4.trans.shared.b16 {%0,%1,%2,%3}, [%4];"
                 : "=r"(r0), "=r"(r1), "=r"(r2), "=r"(r3) : "r"(a));
}
__device__ __forceinline__ void mma_bf16(float* c, uint32_t a0, uint32_t a1, uint32_t a2, uint32_t a3,
                                         uint32_t b0, uint32_t b1) {
    asm volatile(
        "mma.sync.aligned.m16n8k16.row.col.f32.bf16.bf16.f32 "
        "{%0,%1,%2,%3}, {%4,%5,%6,%7}, {%8,%9}, {%0,%1,%2,%3};"
        : "+f"(c[0]), "+f"(c[1]), "+f"(c[2]), "+f"(c[3])
        : "r"(a0), "r"(a1), "r"(a2), "r"(a3), "r"(b0), "r"(b1));
}

// ---------------- init ----------------
__global__ void init_kernel() {
    int i = blockIdx.x * 256 + threadIdx.x;
    if (i < NCOLS) { g_colmap[i] = -1; g_partial[i] = 0.f; }
    if (i < 2) g_cnt[i] = 0;
}

// ---------------- column grouping by polarity sign ----------------
__global__ void prep_cols_kernel(const float* __restrict__ polw) {
    int d = blockIdx.x * 256 + threadIdx.x;
    if (d >= DDIM) return;
    float s = polw[d] * polw[DDIM + d];
    int grp = (s > 0.f) ? 0 : 1;
    int slot = atomicAdd(&g_cnt[grp], 1);
    int col = grp * GCAP + slot;
    g_dcol[d] = col;
    g_colmap[col] = d;
}

// ---------------- A±: 2-limb bf16 split ----------------
__global__ void prep_a_kernel(const float* __restrict__ hist) {
    int i = blockIdx.x * blockDim.x + threadIdx.x;
    long long e = (long long)i * 4;
    if (e >= (long long)MPAD * KDIM) return;
    int t = (int)(e / KDIM), n = (int)(e % KDIM);
    float ap[4] = {0, 0, 0, 0}, am[4] = {0, 0, 0, 0};
    if (t < TDIM) {
        float4 h0 = *reinterpret_cast<const float4*>(hist + ((size_t)t * 2 + 0) * KDIM + n);
        float4 h1 = *reinterpret_cast<const float4*>(hist + ((size_t)t * 2 + 1) * KDIM + n);
        float a0[4] = {h0.x, h0.y, h0.z, h0.w}, a1[4] = {h1.x, h1.y, h1.z, h1.w};
#pragma unroll
        for (int j = 0; j < 4; j++) { ap[j] = a0[j] + a1[j]; am[j] = a0[j] - a1[j]; }
    }
    uint2 pk[4];
#pragma unroll
    for (int g = 0; g < 2; g++) {
        const float* v = g ? am : ap;
        unsigned short hu[4], lu[4];
#pragma unroll
        for (int j = 0; j < 4; j++) {
            __nv_bfloat16 hb = __float2bfloat16_rn(v[j]);
            float r = v[j] - __bfloat162float(hb);
            __nv_bfloat16 lb = __float2bfloat16_rn(r);
            hu[j] = *reinterpret_cast<unsigned short*>(&hb);
            lu[j] = *reinterpret_cast<unsigned short*>(&lb);
        }
        pk[g * 2].x     = (uint32_t)hu[0] | ((uint32_t)hu[1] << 16);
        pk[g * 2].y     = (uint32_t)hu[2] | ((uint32_t)hu[3] << 16);
        pk[g * 2 + 1].x = (uint32_t)lu[0] | ((uint32_t)lu[1] << 16);
        pk[g * 2 + 1].y = (uint32_t)lu[2] | ((uint32_t)lu[3] << 16);
    }
#pragma unroll
    for (int g = 0; g < 2; g++)
#pragma unroll
        for (int l = 0; l < 2; l++)
            *reinterpret_cast<uint2*>(&g_A[g][l][t][n]) = pk[g * 2 + l];
}

// ---------------- epilogue weights Wt[col][m] ----------------
__global__ void prep_w_kernel(const float* __restrict__ timew, const float* __restrict__ polw) {
    long long i = (long long)blockIdx.x * 256 + threadIdx.x;
    if (i >= (long long)NCOLS * MPAD) return;
    int m = (int)(i & 127); int col = (int)(i >> 7);
    int d = g_colmap[col];
    float v = 0.f;
    if (d >= 0 && m < TDIM) v = timew[(size_t)m * DDIM + d] * polw[d];
    g_Wt[i] = v;
}

// ---------------- B chunk: batched-MLP loads, smem scatter, linear write ----------------
__global__ void prep_b_kernel(const float* __restrict__ posw, int koff) {
    __shared__ __align__(16) __nv_bfloat16 sr[NCOLS];
    const int k = koff + blockIdx.x;
    const int tid = threadIdx.x;
    {
        int c0 = g_cnt[0], c1 = g_cnt[1];
        for (int i = c0 + tid; i < GCAP; i += 256) sr[i] = __nv_bfloat16(0.f);
        for (int i = GCAP + c1 + tid; i < NCOLS; i += 256) sr[i] = __nv_bfloat16(0.f);
    }
    __syncthreads();
    const float* row = posw + (size_t)k * DDIM;
#pragma unroll
    for (int h = 0; h < 2; h++) {
        int4 dc[4]; float4 f[4];
#pragma unroll
        for (int i = 0; i < 4; i++) {
            int d0 = tid * 4 + (h * 4 + i) * 1024;
            dc[i] = *reinterpret_cast<const int4*>(g_dcol + d0);
            f[i]  = *reinterpret_cast<const float4*>(row + d0);
        }
#pragma unroll
        for (int i = 0; i < 4; i++) {
            const uint32_t* w = reinterpret_cast<const uint32_t*>(&f[i]);
            const int* dcp = reinterpret_cast<const int*>(&dc[i]);
#pragma unroll
            for (int j = 0; j < 4; j++) {
                unsigned short b = (unsigned short)(w[j] >> 16);   // exact bf16 of +-1.0
                sr[dcp[j]] = *reinterpret_cast<__nv_bfloat16*>(&b);
            }
        }
    }
    __syncthreads();
    uint4* dst = reinterpret_cast<uint4*>(&g_B[(size_t)k * NCOLS]);
    for (int i = tid; i < NCOLS / 8; i += 256)
        dst[i] = reinterpret_cast<const uint4*>(sr)[i];
}

// ---------------- GEMM chunk: NTILE=128 (R15 verbatim) ----------------
__global__ __launch_bounds__(256, 1)
void gemm_kernel(int chunk) {
    extern __shared__ char smem[];
    uint32_t sb = smem_u32(smem);
    const int tid = threadIdx.x, warp = tid >> 5, lane = tid & 31;
    const int dtile = blockIdx.x / KSPLIT;
    const int ks = blockIdx.x % KSPLIT;
    const int col0 = dtile * NTILE;
    const int grp = (col0 >= GCAP) ? 1 : 0;
    const int kbase = chunk * KCHUNK + ks * KPER;
    const __nv_bfloat16* Abase = &g_A[grp][0][0][0];

    float acc[4][4][4];
#pragma unroll
    for (int a = 0; a < 4; a++)
#pragma unroll
        for (int b = 0; b < 4; b++)
#pragma unroll
            for (int c = 0; c < 4; c++) acc[a][b][c] = 0.f;

#define LOAD_STAGE(slot, it) do {                                                   \
        int k0 = kbase + (it) * KTILE;                                              \
        uint32_t sa_ = sb + (slot) * STAGE_BYTES;                                   \
        _Pragma("unroll")                                                           \
        for (int j = 0; j < 8; j++) {       /* A: 2048 16B chunks */                \
            int c = tid + j * 256;                                                  \
            int limb = c >> 10, cc = c & 1023;                                      \
            int row = cc >> 3, ch = cc & 7;                                         \
            const void* src = Abase + ((size_t)limb * MPAD + row) * KDIM + k0 + ch * 8; \
            uint32_t dst = sa_ + limb * 16384 + row * 128 + ((ch * 16) ^ ((row & 7) << 4)); \
            CP_ASYNC(dst, src);                                                     \
        }                                                                           \
        _Pragma("unroll")                                                           \
        for (int j = 0; j < 4; j++) {       /* B: 1024 16B chunks */                \
            int c = tid + j * 256;                                                  \
            int kk = c >> 4, ch = c & 15;                                           \
            const void* src = g_B + (size_t)(k0 + kk) * NCOLS + col0 + ch * 8;      \
            uint32_t dst = sa_ + 32768 + kk * 256 + ((ch * 16) ^ ((kk & 7) << 4));  \
            CP_ASYNC(dst, src);                                                     \
        }                                                                           \
    } while (0)

    LOAD_STAGE(0, 0); CP_COMMIT();
    LOAD_STAGE(1, 1); CP_COMMIT();

    const int wm = warp >> 2, wn = warp & 3;          // 2m x 4n warps, tile m64 x n32
    const int g = lane >> 2, t4 = lane & 3;
    const int aRow = lane & 15;
    const int aKb  = (lane >> 4) << 4;
    const int bK   = ((lane >> 3) & 1) * 8 + (lane & 7);
    const int bNb  = (lane >> 4) << 4;

    for (int it = 0; it < NIT; ++it) {
        CP_WAIT1();
        __syncthreads();
        if (it + 2 < NIT) { LOAD_STAGE((it + 2) % 3, it + 2); }
        CP_COMMIT();

        uint32_t sa = sb + (it % 3) * STAGE_BYTES;
        uint32_t sB = sa + 32768;
#pragma unroll
        for (int kstep = 0; kstep < 4; kstep++) {
            uint32_t bfr[4][2];
#pragma unroll
            for (int ntp = 0; ntp < 2; ntp++) {
                int kr = kstep * 16 + bK;
                int nb = (wn * 32 + ntp * 16) * 2 + bNb;
                uint32_t addr = sB + kr * 256 + (nb ^ ((kr & 7) << 4));
                ldsm_x4_t(bfr[2 * ntp][0], bfr[2 * ntp][1], bfr[2 * ntp + 1][0], bfr[2 * ntp + 1][1], addr);
            }
#pragma unroll
            for (int l = 0; l < 2; l++) {
#pragma unroll
                for (int mt = 0; mt < 4; mt++) {
                    int row = wm * 64 + mt * 16 + aRow;
                    int kb = kstep * 32 + aKb;
                    uint32_t addr = sa + l * 16384 + row * 128 + (kb ^ ((row & 7) << 4));
                    uint32_t a0, a1, a2, a3;
                    ldsm_x4(a0, a1, a2, a3, addr);
#pragma unroll
                    for (int nt = 0; nt < 4; nt++)
                        mma_bf16(acc[mt][nt], a0, a1, a2, a3, bfr[nt][0], bfr[nt][1]);
                }
            }
        }
    }
    CP_WAIT0();
    __syncthreads();

    // ---------------- epilogue ----------------
    float* epi = reinterpret_cast<float*>(smem);
    if (tid < NTILE) epi[tid] = 0.f;
    __syncthreads();

    float cs[4][2];
#pragma unroll
    for (int nt = 0; nt < 4; nt++) { cs[nt][0] = 0.f; cs[nt][1] = 0.f; }
#pragma unroll
    for (int mt = 0; mt < 4; mt++) {
        int r0 = wm * 64 + mt * 16 + g;
        int r1 = r0 + 8;
#pragma unroll
        for (int nt = 0; nt < 4; nt++) {
            int col = col0 + wn * 32 + nt * 8 + t4 * 2;
            float w00 = g_Wt[(size_t)col * MPAD + r0];
            float w01 = g_Wt[(size_t)(col + 1) * MPAD + r0];
            float w10 = g_Wt[(size_t)col * MPAD + r1];
            float w11 = g_Wt[(size_t)(col + 1) * MPAD + r1];
            cs[nt][0] += acc[mt][nt][0] * w00 + acc[mt][nt][2] * w10;
            cs[nt][1] += acc[mt][nt][1] * w01 + acc[mt][nt][3] * w11;
        }
    }
#pragma unroll
    for (int off = 4; off < 32; off <<= 1) {
#pragma unroll
        for (int nt = 0; nt < 4; nt++) {
            cs[nt][0] += __shfl_xor_sync(0xffffffffu, cs[nt][0], off);
            cs[nt][1] += __shfl_xor_sync(0xffffffffu, cs[nt][1], off);
        }
    }
    if (lane < 4) {
#pragma unroll
        for (int nt = 0; nt < 4; nt++) {
            atomicAdd(&epi[wn * 32 + nt * 8 + lane * 2],     cs[nt][0]);
            atomicAdd(&epi[wn * 32 + nt * 8 + lane * 2 + 1], cs[nt][1]);
        }
    }
    __syncthreads();
    if (tid < NTILE) atomicAdd(&g_partial[col0 + tid], epi[tid]);
}

// ---------------- sign ----------------
__global__ void sign_kernel(float* __restrict__ out) {
    int d = blockIdx.x * 256 + threadIdx.x;
    float v = g_partial[g_dcol[d]];
    out[d] = (v > 0.f) ? 1.f : ((v < 0.f) ? -1.f : 0.f);
}

// ---------------- launch: stream-forked pipeline ----------------
extern "C" void kernel_launch(void* const* d_in, const int* in_sizes, int n_in,
                              void* d_out, int out_size) {
    (void)in_sizes; (void)n_in; (void)out_size;
    const float* hist  = (const float*)d_in[0];   // [100,2,128,128]
    const float* timew = (const float*)d_in[1];   // [100,8192]
    const float* polw  = (const float*)d_in[2];   // [2,8192]
    const float* posw  = (const float*)d_in[3];   // [16384,8192]
    float* out = (float*)d_out;                   // [8192]

    static cudaStream_t sP = nullptr;
    static cudaEvent_t evFork, evPb[NCHUNK];
    if (sP == nullptr) {
        cudaStreamCreateWithFlags(&sP, cudaStreamNonBlocking);
        cudaEventCreateWithFlags(&evFork, cudaEventDisableTiming);
        for (int c = 0; c < NCHUNK; c++)
            cudaEventCreateWithFlags(&evPb[c], cudaEventDisableTiming);
        cudaFuncSetAttribute(gemm_kernel, cudaFuncAttributeMaxDynamicSharedMemorySize, SMEM_MAIN);
        // align L1/smem carveouts so prep_b CTAs can co-reside with gemm CTAs
        cudaFuncSetAttribute(gemm_kernel, cudaFuncAttributePreferredSharedMemoryCarveout,
                             cudaSharedmemCarveoutMaxShared);
        cudaFuncSetAttribute(prep_b_kernel, cudaFuncAttributePreferredSharedMemoryCarveout,
                             cudaSharedmemCarveoutMaxShared);
    }

    // main stream: setup
    init_kernel<<<(NCOLS + 255) / 256, 256>>>();
    prep_cols_kernel<<<DDIM / 256, 256>>>(polw);

    // fork branch P: B production in 4 chunks
    cudaEventRecord(evFork, 0);
    cudaStreamWaitEvent(sP, evFork, 0);
    for (int c = 0; c < NCHUNK; c++) {
        prep_b_kernel<<<KCHUNK, 256, 0, sP>>>(posw, c * KCHUNK);
        cudaEventRecord(evPb[c], sP);
    }

    // main stream: A and W prep (overlaps chunk 0 of branch P)
    prep_a_kernel<<<(MPAD * KDIM / 4 + 255) / 256, 256>>>(hist);
    prep_w_kernel<<<(int)(((long long)NCOLS * MPAD + 255) / 256), 256>>>(timew, polw);

    // main stream: GEMM chunks, each gated on its B chunk (joins branch P)
    for (int c = 0; c < NCHUNK; c++) {
        cudaStreamWaitEvent(0, evPb[c], 0);
        gemm_kernel<<<(NCOLS / NTILE) * KSPLIT, 256, SMEM_MAIN>>>(c);
    }

    sign_kernel<<<DDIM / 256, 256>>>(out);
}

// round 17
// speedup vs baseline: 1.1042x; 1.1042x over previous
#include <cuda_runtime.h>
#include <cuda_bf16.h>
#include <stdint.h>

// ---- problem dims ----
#define TDIM 100
#define MPAD 128
#define KDIM 16384
#define DDIM 8192
#define GCAP 4352
#define NCOLS (2*GCAP)            // 8704

// ---- GEMM tiling: NTILE=128, direct-B gather, full K per CTA half ----
#define NTILE 128
#define KTILE 64
#define KSPLIT 2
#define KPER  (KDIM/KSPLIT)       // 8192
#define NIT   (KPER/KTILE)        // 128
#define STAGE_BYTES 49152         // A: 2 limbs * 16KB + B: 16KB
#define SM_DMAP (3*STAGE_BYTES)   // 147456: 128 ints
#define SMEM_MAIN (SM_DMAP + 512) // 147968

// ---- scratch ----
__device__ __nv_bfloat16 g_A[2][2][MPAD][KDIM];          // [grp][limb] 16MB
__device__ float         g_Wt[(size_t)NCOLS * MPAD];     // [col][m]
__device__ int           g_dcol[DDIM];
__device__ int           g_colmap[NCOLS];
__device__ float         g_partial[NCOLS];

// ---- PTX helpers ----
__device__ __forceinline__ uint32_t smem_u32(const void* p) {
    uint32_t a;
    asm("{ .reg .u64 t; cvta.to.shared.u64 t, %1; cvt.u32.u64 %0, t; }" : "=r"(a) : "l"(p));
    return a;
}
#define CP_ASYNC(dst, src) asm volatile("cp.async.cg.shared.global [%0], [%1], 16;" :: "r"(dst), "l"(src))
#define CP_COMMIT()        asm volatile("cp.async.commit_group;")
#define CP_WAIT1()         asm volatile("cp.async.wait_group 1;")
#define CP_WAIT0()         asm volatile("cp.async.wait_group 0;")

__device__ __forceinline__ void ldsm_x4(uint32_t& r0, uint32_t& r1, uint32_t& r2, uint32_t& r3, uint32_t a) {
    asm volatile("ldmatrix.sync.aligned.m8n8.x4.shared.b16 {%0,%1,%2,%3}, [%4];"
                 : "=r"(r0), "=r"(r1), "=r"(r2), "=r"(r3) : "r"(a));
}
__device__ __forceinline__ void ldsm_x4_t(uint32_t& r0, uint32_t& r1, uint32_t& r2, uint32_t& r3, uint32_t a) {
    asm volatile("ldmatrix.sync.aligned.m8n8.x4.trans.shared.b16 {%0,%1,%2,%3}, [%4];"
                 : "=r"(r0), "=r"(r1), "=r"(r2), "=r"(r3) : "r"(a));
}
__device__ __forceinline__ void mma_bf16(float* c, uint32_t a0, uint32_t a1, uint32_t a2, uint32_t a3,
                                         uint32_t b0, uint32_t b1) {
    asm volatile(
        "mma.sync.aligned.m16n8k16.row.col.f32.bf16.bf16.f32 "
        "{%0,%1,%2,%3}, {%4,%5,%6,%7}, {%8,%9}, {%0,%1,%2,%3};"
        : "+f"(c[0]), "+f"(c[1]), "+f"(c[2]), "+f"(c[3])
        : "r"(a0), "r"(a1), "r"(a2), "r"(a3), "r"(b0), "r"(b1));
}

// ---------------- init ----------------
__global__ void init_kernel() {
    int i = blockIdx.x * 256 + threadIdx.x;
    if (i < NCOLS) { g_colmap[i] = -1; g_partial[i] = 0.f; }
}

// ---------------- stable (d-ordered) column grouping: single block, 1024 threads ----------------
__global__ void prep_cols_kernel(const float* __restrict__ polw) {
    __shared__ int wsum[32];
    const int tid = threadIdx.x;             // 1024 threads, 8 d's each
    const int base = tid * 8;
    int flags[8];
    int cnt = 0;
#pragma unroll
    for (int j = 0; j < 8; j++) {
        int d = base + j;
        float s = polw[d] * polw[DDIM + d];
        flags[j] = (s > 0.f) ? 0 : 1;
        cnt += flags[j];
    }
    const int lane = tid & 31, wid = tid >> 5;
    int v = cnt;
#pragma unroll
    for (int off = 1; off < 32; off <<= 1) {
        int o = __shfl_up_sync(0xffffffffu, v, off);
        if (lane >= off) v += o;
    }
    if (lane == 31) wsum[wid] = v;
    __syncthreads();
    if (tid < 32) {
        int w = wsum[tid];
#pragma unroll
        for (int off = 1; off < 32; off <<= 1) {
            int o = __shfl_up_sync(0xffffffffu, w, off);
            if (tid >= off) w += o;
        }
        wsum[tid] = w;
    }
    __syncthreads();
    int c1before = (v - cnt) + (wid > 0 ? wsum[wid - 1] : 0);
#pragma unroll
    for (int j = 0; j < 8; j++) {
        int d = base + j;
        int col = flags[j] ? (GCAP + c1before) : (d - c1before);
        g_dcol[d] = col;
        g_colmap[col] = d;
        c1before += flags[j];
    }
}

// ---------------- A±: 2-limb bf16 split ----------------
__global__ void prep_a_kernel(const float* __restrict__ hist) {
    int i = blockIdx.x * blockDim.x + threadIdx.x;
    long long e = (long long)i * 4;
    if (e >= (long long)MPAD * KDIM) return;
    int t = (int)(e / KDIM), n = (int)(e % KDIM);
    float ap[4] = {0, 0, 0, 0}, am[4] = {0, 0, 0, 0};
    if (t < TDIM) {
        float4 h0 = *reinterpret_cast<const float4*>(hist + ((size_t)t * 2 + 0) * KDIM + n);
        float4 h1 = *reinterpret_cast<const float4*>(hist + ((size_t)t * 2 + 1) * KDIM + n);
        float a0[4] = {h0.x, h0.y, h0.z, h0.w}, a1[4] = {h1.x, h1.y, h1.z, h1.w};
#pragma unroll
        for (int j = 0; j < 4; j++) { ap[j] = a0[j] + a1[j]; am[j] = a0[j] - a1[j]; }
    }
    uint2 pk[4];
#pragma unroll
    for (int g = 0; g < 2; g++) {
        const float* v = g ? am : ap;
        unsigned short hu[4], lu[4];
#pragma unroll
        for (int j = 0; j < 4; j++) {
            __nv_bfloat16 hb = __float2bfloat16_rn(v[j]);
            float r = v[j] - __bfloat162float(hb);
            __nv_bfloat16 lb = __float2bfloat16_rn(r);
            hu[j] = *reinterpret_cast<unsigned short*>(&hb);
            lu[j] = *reinterpret_cast<unsigned short*>(&lb);
        }
        pk[g * 2].x     = (uint32_t)hu[0] | ((uint32_t)hu[1] << 16);
        pk[g * 2].y     = (uint32_t)hu[2] | ((uint32_t)hu[3] << 16);
        pk[g * 2 + 1].x = (uint32_t)lu[0] | ((uint32_t)lu[1] << 16);
        pk[g * 2 + 1].y = (uint32_t)lu[2] | ((uint32_t)lu[3] << 16);
    }
#pragma unroll
    for (int g = 0; g < 2; g++)
#pragma unroll
        for (int l = 0; l < 2; l++)
            *reinterpret_cast<uint2*>(&g_A[g][l][t][n]) = pk[g * 2 + l];
}

// ---------------- epilogue weights Wt[col][m] ----------------
__global__ void prep_w_kernel(const float* __restrict__ timew, const float* __restrict__ polw) {
    long long i = (long long)blockIdx.x * 256 + threadIdx.x;
    if (i >= (long long)NCOLS * MPAD) return;
    int m = (int)(i & 127); int col = (int)(i >> 7);
    int d = g_colmap[col];
    float v = 0.f;
    if (d >= 0 && m < TDIM) v = timew[(size_t)m * DDIM + d] * polw[d];
    g_Wt[i] = v;
}

// ---------------- GEMM: direct-B gather from posw (no g_B) ----------------
__global__ __launch_bounds__(256, 1)
void gemm_kernel(const float* __restrict__ posw) {
    extern __shared__ char smem[];
    uint32_t sb = smem_u32(smem);
    const int tid = threadIdx.x, warp = tid >> 5, lane = tid & 31;
    const int dtile = blockIdx.x / KSPLIT;
    const int ks = blockIdx.x % KSPLIT;
    const int col0 = dtile * NTILE;
    const int grp = (col0 >= GCAP) ? 1 : 0;
    const int kbase = ks * KPER;
    const __nv_bfloat16* Abase = &g_A[grp][0][0][0];

    // per-tile column->d map in smem
    int* sdmap = reinterpret_cast<int*>(smem + SM_DMAP);
    if (tid < NTILE) sdmap[tid] = g_colmap[col0 + tid];
    __syncthreads();

    // B gather ownership: 2 adjacent cols x 16 k's per thread
    const int cpair = tid & 63;          // col pair index (cols 2c, 2c+1)
    const int kq = tid >> 6;             // k quarter (16 of 64)
    const int dm0 = sdmap[2 * cpair];
    const int dm1 = sdmap[2 * cpair + 1];
    const uint32_t cp4 = 4 * cpair;      // byte offset of col pair within 256B row

    float acc[4][4][4];
#pragma unroll
    for (int a = 0; a < 4; a++)
#pragma unroll
        for (int b = 0; b < 4; b++)
#pragma unroll
            for (int c = 0; c < 4; c++) acc[a][b][c] = 0.f;

    uint32_t rb0[16], rb1[16];

#define LDG_B(it) do {                                                              \
        int kk0 = kbase + (it) * KTILE + kq * 16;                                   \
        _Pragma("unroll")                                                           \
        for (int i = 0; i < 16; i++) {                                              \
            size_t off = (size_t)(kk0 + i) * DDIM;                                  \
            rb0[i] = (dm0 >= 0) ? __float_as_uint(__ldg(posw + off + dm0)) : 0u;    \
            rb1[i] = (dm1 >= 0) ? __float_as_uint(__ldg(posw + off + dm1)) : 0u;    \
        }                                                                           \
    } while (0)

#define STS_B(slot) do {                                                            \
        uint32_t bbase = sb + (slot) * STAGE_BYTES + 32768;                         \
        _Pragma("unroll")                                                           \
        for (int i = 0; i < 16; i++) {                                              \
            uint32_t kk = kq * 16 + i;                                              \
            uint32_t v = (rb0[i] >> 16) | (rb1[i] & 0xFFFF0000u);                   \
            uint32_t addr = bbase + kk * 256 + (cp4 ^ ((kk & 7) << 4));             \
            asm volatile("st.shared.b32 [%0], %1;" :: "r"(addr), "r"(v) : "memory"); \
        }                                                                           \
    } while (0)

#define LOAD_A(slot, it) do {                                                       \
        int k0 = kbase + (it) * KTILE;                                              \
        uint32_t sa_ = sb + (slot) * STAGE_BYTES;                                   \
        _Pragma("unroll")                                                           \
        for (int j = 0; j < 8; j++) {       /* A: 2048 16B chunks */                \
            int c = tid + j * 256;                                                  \
            int limb = c >> 10, cc = c & 1023;                                      \
            int row = cc >> 3, ch = cc & 7;                                         \
            const void* src = Abase + ((size_t)limb * MPAD + row) * KDIM + k0 + ch * 8; \
            uint32_t dst = sa_ + limb * 16384 + row * 128 + ((ch * 16) ^ ((row & 7) << 4)); \
            CP_ASYNC(dst, src);                                                     \
        }                                                                           \
    } while (0)

    // prologue: B stages 0,1 via gather, A stages 0,1 via cp.async
    LDG_B(0); STS_B(0);
    LDG_B(1); STS_B(1);
    LOAD_A(0, 0); CP_COMMIT();
    LOAD_A(1, 1); CP_COMMIT();

    const int wm = warp >> 2, wn = warp & 3;          // 2m x 4n warps, tile m64 x n32
    const int g = lane >> 2, t4 = lane & 3;
    const int aRow = lane & 15;
    const int aKb  = (lane >> 4) << 4;
    const int bK   = ((lane >> 3) & 1) * 8 + (lane & 7);
    const int bNb  = (lane >> 4) << 4;

    for (int it = 0; it < NIT; ++it) {
        CP_WAIT1();
        __syncthreads();
        const bool pre = (it + 2 < NIT);
        if (pre) LDG_B(it + 2);

        uint32_t sa = sb + (it % 3) * STAGE_BYTES;
        uint32_t sB = sa + 32768;
#pragma unroll
        for (int kstep = 0; kstep < 4; kstep++) {
            uint32_t bfr[4][2];
#pragma unroll
            for (int ntp = 0; ntp < 2; ntp++) {
                int kr = kstep * 16 + bK;
                int nb = (wn * 32 + ntp * 16) * 2 + bNb;
                uint32_t addr = sB + kr * 256 + (nb ^ ((kr & 7) << 4));
                ldsm_x4_t(bfr[2 * ntp][0], bfr[2 * ntp][1], bfr[2 * ntp + 1][0], bfr[2 * ntp + 1][1], addr);
            }
#pragma unroll
            for (int l = 0; l < 2; l++) {
#pragma unroll
                for (int mt = 0; mt < 4; mt++) {
                    int row = wm * 64 + mt * 16 + aRow;
                    int kb = kstep * 32 + aKb;
                    uint32_t addr = sa + l * 16384 + row * 128 + (kb ^ ((row & 7) << 4));
                    uint32_t a0, a1, a2, a3;
                    ldsm_x4(a0, a1, a2, a3, addr);
#pragma unroll
                    for (int nt = 0; nt < 4; nt++)
                        mma_bf16(acc[mt][nt], a0, a1, a2, a3, bfr[nt][0], bfr[nt][1]);
                }
            }
        }
        if (pre) {
            STS_B((it + 2) % 3);
            LOAD_A((it + 2) % 3, it + 2);
        }
        CP_COMMIT();
    }
    CP_WAIT0();
    __syncthreads();

    // ---------------- epilogue ----------------
    float* epi = reinterpret_cast<float*>(smem);
    if (tid < NTILE) epi[tid] = 0.f;
    __syncthreads();

    float cs[4][2];
#pragma unroll
    for (int nt = 0; nt < 4; nt++) { cs[nt][0] = 0.f; cs[nt][1] = 0.f; }
#pragma unroll
    for (int mt = 0; mt < 4; mt++) {
        int r0 = wm * 64 + mt * 16 + g;
        int r1 = r0 + 8;
#pragma unroll
        for (int nt = 0; nt < 4; nt++) {
            int col = col0 + wn * 32 + nt * 8 + t4 * 2;
            float w00 = g_Wt[(size_t)col * MPAD + r0];
            float w01 = g_Wt[(size_t)(col + 1) * MPAD + r0];
            float w10 = g_Wt[(size_t)col * MPAD + r1];
            float w11 = g_Wt[(size_t)(col + 1) * MPAD + r1];
            cs[nt][0] += acc[mt][nt][0] * w00 + acc[mt][nt][2] * w10;
            cs[nt][1] += acc[mt][nt][1] * w01 + acc[mt][nt][3] * w11;
        }
    }
#pragma unroll
    for (int off = 4; off < 32; off <<= 1) {
#pragma unroll
        for (int nt = 0; nt < 4; nt++) {
            cs[nt][0] += __shfl_xor_sync(0xffffffffu, cs[nt][0], off);
            cs[nt][1] += __shfl_xor_sync(0xffffffffu, cs[nt][1], off);
        }
    }
    if (lane < 4) {
#pragma unroll
        for (int nt = 0; nt < 4; nt++) {
            atomicAdd(&epi[wn * 32 + nt * 8 + lane * 2],     cs[nt][0]);
            atomicAdd(&epi[wn * 32 + nt * 8 + lane * 2 + 1], cs[nt][1]);
        }
    }
    __syncthreads();
    if (tid < NTILE) atomicAdd(&g_partial[col0 + tid], epi[tid]);
}

// ---------------- sign ----------------
__global__ void sign_kernel(float* __restrict__ out) {
    int d = blockIdx.x * 256 + threadIdx.x;
    float v = g_partial[g_dcol[d]];
    out[d] = (v > 0.f) ? 1.f : ((v < 0.f) ? -1.f : 0.f);
}

// ---------------- launch ----------------
extern "C" void kernel_launch(void* const* d_in, const int* in_sizes, int n_in,
                              void* d_out, int out_size) {
    (void)in_sizes; (void)n_in; (void)out_size;
    const float* hist  = (const float*)d_in[0];   // [100,2,128,128]
    const float* timew = (const float*)d_in[1];   // [100,8192]
    const float* polw  = (const float*)d_in[2];   // [2,8192]
    const float* posw  = (const float*)d_in[3];   // [16384,8192]
    float* out = (float*)d_out;                   // [8192]

    cudaFuncSetAttribute(gemm_kernel, cudaFuncAttributeMaxDynamicSharedMemorySize, SMEM_MAIN);

    init_kernel<<<(NCOLS + 255) / 256, 256>>>();
    prep_cols_kernel<<<1, 1024>>>(polw);
    prep_a_kernel<<<(MPAD * KDIM / 4 + 255) / 256, 256>>>(hist);
    prep_w_kernel<<<(int)(((long long)NCOLS * MPAD + 255) / 256), 256>>>(timew, polw);
    gemm_kernel<<<(NCOLS / NTILE) * KSPLIT, 256, SMEM_MAIN>>>(posw);
    sign_kernel<<<DDIM / 256, 256>>>(out);
}